// round 15
// baseline (speedup 1.0000x reference)
#include <cuda_runtime.h>
#include <cuda_bf16.h>
#include <math.h>
#include <stdint.h>

#define B_ 16
#define N_ 1024
#define D_ 2048
#define E_ 8
#define H_ 512
#define A_ 256
#define L_ 64
#define C_ 8
#define NPAIR 32   // B_ * TOP_K

// ---- scratch (static device globals; no allocation anywhere) ----
__device__ float g_r[B_ * H_];
__device__ float g_scores[NPAIR * N_];
__device__ float g_pooled[NPAIR * H_];
__device__ int   g_sel_e[NPAIR];
__device__ float g_sel_w[NPAIR];
__device__ __nv_bfloat16 g_xhi[(size_t)B_ * N_ * D_];  // 64 MB
__device__ __nv_bfloat16 g_xlo[(size_t)B_ * N_ * D_];  // 64 MB
__device__ __nv_bfloat16 g_hhi[(size_t)NPAIR * N_ * H_];  // 32 MB
__device__ __nv_bfloat16 g_hlo[(size_t)NPAIR * N_ * H_];  // 32 MB
__device__ __nv_bfloat16 g_w1t_hi[(size_t)E_ * H_ * D_];
__device__ __nv_bfloat16 g_w1t_lo[(size_t)E_ * H_ * D_];
__device__ __nv_bfloat16 g_rwt_hi[(size_t)H_ * D_];
__device__ __nv_bfloat16 g_rwt_lo[(size_t)H_ * D_];
// combined Wv|Wu, layout [e][4 blocks][64 V-rows + 64 U-rows][H]
__device__ __nv_bfloat16 g_wvu_hi[(size_t)E_ * 512 * H_];
__device__ __nv_bfloat16 g_wvu_lo[(size_t)E_ * 512 * H_];

// ======================= base-PTX helpers =======================
__device__ __forceinline__ uint32_t smem_to_u32(const void* p) {
    uint32_t a;
    asm("{ .reg .u64 t; cvta.to.shared.u64 t, %1; cvt.u32.u64 %0, t; }"
        : "=r"(a) : "l"(p));
    return a;
}
__device__ __forceinline__ void cp_async16(uint32_t dst, const void* src) {
    asm volatile("cp.async.ca.shared.global [%0], [%1], 16;"
                 :: "r"(dst), "l"(src) : "memory");
}
#define CP_COMMIT() asm volatile("cp.async.commit_group;" ::: "memory")
#define CP_WAIT1()  asm volatile("cp.async.wait_group 1;" ::: "memory")

__device__ __forceinline__ void ldmx4(uint32_t* r, uint32_t addr) {
    asm volatile("ldmatrix.sync.aligned.m8n8.x4.shared.b16 {%0,%1,%2,%3}, [%4];"
        : "=r"(r[0]), "=r"(r[1]), "=r"(r[2]), "=r"(r[3]) : "r"(addr));
}
__device__ __forceinline__ void mma_bf16(float* c, const uint32_t* a,
                                         const uint32_t* b) {
    asm volatile(
        "mma.sync.aligned.m16n8k16.row.col.f32.bf16.bf16.f32 "
        "{%0,%1,%2,%3}, {%4,%5,%6,%7}, {%8,%9}, {%0,%1,%2,%3};"
        : "+f"(c[0]), "+f"(c[1]), "+f"(c[2]), "+f"(c[3])
        : "r"(a[0]), "r"(a[1]), "r"(a[2]), "r"(a[3]),
          "r"(b[0]), "r"(b[1]));
}

// ======================= conversion kernels =======================
__global__ __launch_bounds__(256) void k_conv_x(const float* __restrict__ x) {
    size_t i = ((size_t)blockIdx.x * 256 + threadIdx.x) * 4;
    float4 v = *(const float4*)(x + i);
    __nv_bfloat16 h0 = __float2bfloat16(v.x), h1 = __float2bfloat16(v.y);
    __nv_bfloat16 h2 = __float2bfloat16(v.z), h3 = __float2bfloat16(v.w);
    __nv_bfloat16 l0 = __float2bfloat16(v.x - __bfloat162float(h0));
    __nv_bfloat16 l1 = __float2bfloat16(v.y - __bfloat162float(h1));
    __nv_bfloat16 l2 = __float2bfloat16(v.z - __bfloat162float(h2));
    __nv_bfloat16 l3 = __float2bfloat16(v.w - __bfloat162float(h3));
    *(__nv_bfloat162*)(g_xhi + i)     = __nv_bfloat162(h0, h1);
    *(__nv_bfloat162*)(g_xhi + i + 2) = __nv_bfloat162(h2, h3);
    *(__nv_bfloat162*)(g_xlo + i)     = __nv_bfloat162(l0, l1);
    *(__nv_bfloat162*)(g_xlo + i + 2) = __nv_bfloat162(l2, l3);
}

// transpose + split W1: src [D_,H_] row-major -> dst [H_,D_] (K-major)
__global__ void k_conv_w(const float* __restrict__ routerW,
                         const float* __restrict__ eW1) {
    __shared__ float t[32][33];
    const int z = blockIdx.z;
    const float* src = z ? (eW1 + (size_t)(z - 1) * D_ * H_) : routerW;
    __nv_bfloat16* dh = z ? (g_w1t_hi + (size_t)(z - 1) * H_ * D_) : g_rwt_hi;
    __nv_bfloat16* dl = z ? (g_w1t_lo + (size_t)(z - 1) * H_ * D_) : g_rwt_lo;
    const int k0 = blockIdx.x * 32, n0 = blockIdx.y * 32;
    #pragma unroll
    for (int i = 0; i < 4; i++) {
        int k = k0 + threadIdx.y + i * 8;
        t[threadIdx.y + i * 8][threadIdx.x] = src[(size_t)k * H_ + n0 + threadIdx.x];
    }
    __syncthreads();
    #pragma unroll
    for (int i = 0; i < 4; i++) {
        int n = n0 + threadIdx.y + i * 8;
        float v = t[threadIdx.x][threadIdx.y + i * 8];
        __nv_bfloat16 hv = __float2bfloat16(v);
        __nv_bfloat16 lv = __float2bfloat16(v - __bfloat162float(hv));
        dh[(size_t)n * D_ + k0 + threadIdx.x] = hv;
        dl[(size_t)n * D_ + k0 + threadIdx.x] = lv;
    }
}

// transpose + split Wv/Wu into combined layout:
// dst row for a-col a: (a>>6)*128 + (a&63) + 64*isU  (within expert e)
__global__ void k_conv_wsc(const float* __restrict__ eWv,
                           const float* __restrict__ eWu) {
    __shared__ float t[32][33];
    const int z = blockIdx.z;
    const int e = z & 7, isU = z >> 3;
    const float* src = (isU ? eWu : eWv) + (size_t)e * H_ * A_;
    const int h0 = blockIdx.x * 32, a0 = blockIdx.y * 32;
    #pragma unroll
    for (int i = 0; i < 4; i++) {
        int h = h0 + threadIdx.y + i * 8;
        t[threadIdx.y + i * 8][threadIdx.x] = src[(size_t)h * A_ + a0 + threadIdx.x];
    }
    __syncthreads();
    #pragma unroll
    for (int i = 0; i < 4; i++) {
        int a = a0 + threadIdx.y + i * 8;
        float v = t[threadIdx.x][threadIdx.y + i * 8];
        __nv_bfloat16 hv = __float2bfloat16(v);
        __nv_bfloat16 lv = __float2bfloat16(v - __bfloat162float(hv));
        size_t row = (size_t)e * 512 + (a >> 6) * 128 + (a & 63) + 64 * isU;
        g_wvu_hi[row * H_ + h0 + threadIdx.x] = hv;
        g_wvu_lo[row * H_ + h0 + threadIdx.x] = lv;
    }
}

// ======================= mma.sync GEMM core (swizzled, 3-stage) ============
// Block tile 128x128, K-chunks of 32 bf16 (64 B/row). 8 warps, warp tile 32x64.
// smem row = 64 B, chunk swizzle: c ^= (row>>1)&3  -> conflict-free ldmatrix.
#define ARRB   (128 * 64)       // 8192
#define STAGEB (4 * ARRB)       // 32768
#define NSTG   3
#define MM_SMEM (NSTG * STAGEB) // 98304 -> 2 CTAs/SM

__device__ __forceinline__ uint32_t swz(int row, int chunk) {
    return (uint32_t)(row * 64 + ((chunk ^ ((row >> 1) & 3)) << 4));
}

template<int LDK>
__device__ __forceinline__ void mm_load_stage(
    uint32_t sb, int stg, int k0, int tid,
    const __nv_bfloat16* Ah, const __nv_bfloat16* Al,
    const __nv_bfloat16* Bh, const __nv_bfloat16* Bl) {
    const __nv_bfloat16* ps[4] = {Ah, Al, Bh, Bl};
    uint32_t base = sb + stg * STAGEB;
    int row0 = tid >> 2, c = tid & 3;
    #pragma unroll
    for (int arr = 0; arr < 4; arr++) {
        #pragma unroll
        for (int half = 0; half < 2; half++) {
            int row = row0 + half * 64;
            cp_async16(base + arr * ARRB + swz(row, c),
                       ps[arr] + (size_t)row * LDK + k0 + c * 8);
        }
    }
}

template<int LDK, int NCHUNK>
__device__ __forceinline__ void mm_core(
    const __nv_bfloat16* __restrict__ Ah, const __nv_bfloat16* __restrict__ Al,
    const __nv_bfloat16* __restrict__ Bh, const __nv_bfloat16* __restrict__ Bl,
    uint32_t sb, int tid, float acc[2][8][4]) {
    const int lane = tid & 31, wid = tid >> 5;
    const int wm = wid & 3, wn = wid >> 2;

    mm_load_stage<LDK>(sb, 0, 0, tid, Ah, Al, Bh, Bl);  CP_COMMIT();
    mm_load_stage<LDK>(sb, 1, 32, tid, Ah, Al, Bh, Bl); CP_COMMIT();

    const int a_row = lane & 15, a_ch = lane >> 4;       // chunk bit
    const int b_row = ((lane >> 4) & 1) * 8 + (lane & 7);
    const int b_ch = (lane >> 3) & 1;

    for (int s = 0; s < NCHUNK; s++) {
        CP_WAIT1();
        __syncthreads();
        if (s + 2 < NCHUNK)
            mm_load_stage<LDK>(sb, (s + 2) % NSTG, (s + 2) * 32, tid, Ah, Al, Bh, Bl);
        CP_COMMIT();

        const uint32_t b0 = sb + (s % NSTG) * STAGEB;
        #pragma unroll
        for (int ks = 0; ks < 2; ks++) {       // two k16 slices
            uint32_t ah[2][4], al[2][4], bh[8][2], bl[8][2];
            uint32_t ra[2], rb4[4];
            #pragma unroll
            for (int mt = 0; mt < 2; mt++) {
                ra[mt] = b0 + swz(wm * 32 + mt * 16 + a_row, ks * 2 + a_ch);
                ldmx4(ah[mt], ra[mt]);
            }
            #pragma unroll
            for (int np = 0; np < 4; np++) {
                rb4[np] = b0 + 2 * ARRB + swz(wn * 64 + np * 16 + b_row, ks * 2 + b_ch);
                ldmx4(&bh[2 * np][0], rb4[np]);
            }
            #pragma unroll
            for (int mt = 0; mt < 2; mt++)
                #pragma unroll
                for (int nt = 0; nt < 8; nt++)
                    mma_bf16(acc[mt][nt], ah[mt], bh[nt]);
            #pragma unroll
            for (int mt = 0; mt < 2; mt++)
                ldmx4(al[mt], ra[mt] + ARRB);
            #pragma unroll
            for (int mt = 0; mt < 2; mt++)
                #pragma unroll
                for (int nt = 0; nt < 8; nt++)
                    mma_bf16(acc[mt][nt], al[mt], bh[nt]);
            #pragma unroll
            for (int np = 0; np < 4; np++)
                ldmx4(&bl[2 * np][0], rb4[np] + ARRB);
            #pragma unroll
            for (int mt = 0; mt < 2; mt++)
                #pragma unroll
                for (int nt = 0; nt < 8; nt++)
                    mma_bf16(acc[mt][nt], ah[mt], bl[nt]);
        }
    }
}

// ---------------------------------------------------------------------------
// K1: router GEMM: relu(x@W + b), mean over N -> atomic into g_r
// ---------------------------------------------------------------------------
__global__ __launch_bounds__(256, 2) void k_mm_router(const float* __restrict__ rb) {
    extern __shared__ char smem[];
    const uint32_t sb = smem_to_u32(smem);
    const int tid = threadIdx.x;
    const int n0 = blockIdx.x * 128, m0 = blockIdx.y * 128;

    float acc[2][8][4] = {};
    mm_core<D_, D_ / 32>(g_xhi + (size_t)m0 * D_, g_xlo + (size_t)m0 * D_,
                         g_rwt_hi + (size_t)n0 * D_, g_rwt_lo + (size_t)n0 * D_,
                         sb, tid, acc);

    const int lane = tid & 31, wid = tid >> 5;
    const int wn = wid >> 2;
    const int l4 = lane >> 2, q2 = (lane & 3) * 2;
    const int b = m0 / N_;
    #pragma unroll
    for (int nt = 0; nt < 8; nt++) {
        int col = n0 + wn * 64 + nt * 8 + q2;
        float bx = rb[col], by = rb[col + 1];
        float s0 = 0.f, s1 = 0.f;
        #pragma unroll
        for (int mt = 0; mt < 2; mt++) {
            s0 += fmaxf(acc[mt][nt][0] + bx, 0.f) + fmaxf(acc[mt][nt][2] + bx, 0.f);
            s1 += fmaxf(acc[mt][nt][1] + by, 0.f) + fmaxf(acc[mt][nt][3] + by, 0.f);
        }
        s0 += __shfl_xor_sync(0xffffffffu, s0, 4);
        s0 += __shfl_xor_sync(0xffffffffu, s0, 8);
        s0 += __shfl_xor_sync(0xffffffffu, s0, 16);
        s1 += __shfl_xor_sync(0xffffffffu, s1, 4);
        s1 += __shfl_xor_sync(0xffffffffu, s1, 8);
        s1 += __shfl_xor_sync(0xffffffffu, s1, 16);
        if (l4 == 0) {
            atomicAdd(&g_r[b * H_ + col],     s0 * (1.f / N_));
            atomicAdd(&g_r[b * H_ + col + 1], s1 * (1.f / N_));
        }
    }
}

// ---------------------------------------------------------------------------
// K3: expert GEMM: h = relu(x_b @ eW1[e] + eb1[e]) -> split-bf16 g_hhi/g_hlo
// ---------------------------------------------------------------------------
__global__ __launch_bounds__(256, 2) void k_mm_expert(const float* __restrict__ eb1) {
    extern __shared__ char smem[];
    const uint32_t sb = smem_to_u32(smem);
    const int tid = threadIdx.x;
    const int pair = blockIdx.z;
    const int e = g_sel_e[pair], b = pair >> 1;
    const int n0 = blockIdx.x * 128, m0 = blockIdx.y * 128;

    float acc[2][8][4] = {};
    mm_core<D_, D_ / 32>(g_xhi + ((size_t)b * N_ + m0) * D_,
                         g_xlo + ((size_t)b * N_ + m0) * D_,
                         g_w1t_hi + ((size_t)e * H_ + n0) * D_,
                         g_w1t_lo + ((size_t)e * H_ + n0) * D_, sb, tid, acc);

    const int lane = tid & 31, wid = tid >> 5;
    const int wm = wid & 3, wn = wid >> 2;
    const int l4 = lane >> 2, q2 = (lane & 3) * 2;
    __nv_bfloat16* hh = g_hhi + (size_t)pair * N_ * H_;
    __nv_bfloat16* hl = g_hlo + (size_t)pair * N_ * H_;
    #pragma unroll
    for (int mt = 0; mt < 2; mt++) {
        #pragma unroll
        for (int rh = 0; rh < 2; rh++) {
            int row = m0 + wm * 32 + mt * 16 + l4 + rh * 8;
            #pragma unroll
            for (int nt = 0; nt < 8; nt++) {
                int col = n0 + wn * 64 + nt * 8 + q2;
                float v0 = fmaxf(acc[mt][nt][2 * rh] + eb1[e * H_ + col], 0.f);
                float v1 = fmaxf(acc[mt][nt][2 * rh + 1] + eb1[e * H_ + col + 1], 0.f);
                __nv_bfloat16 h0 = __float2bfloat16(v0);
                __nv_bfloat16 h1 = __float2bfloat16(v1);
                __nv_bfloat16 l0 = __float2bfloat16(v0 - __bfloat162float(h0));
                __nv_bfloat16 l1 = __float2bfloat16(v1 - __bfloat162float(h1));
                *(__nv_bfloat162*)&hh[(size_t)row * H_ + col] = __nv_bfloat162(h0, h1);
                *(__nv_bfloat162*)&hl[(size_t)row * H_ + col] = __nv_bfloat162(l0, l1);
            }
        }
    }
}

// ---------------------------------------------------------------------------
// K4: merged score GEMM: one pass computes V (cols 0-63) and U (cols 64-127)
// of a 64-a-col block. V warps stash tanh in smem; U warps combine + reduce.
// grid (A_/64=4, N_/128=8, NPAIR)
// ---------------------------------------------------------------------------
__global__ __launch_bounds__(256, 2) void k_mm_score(
    const float* __restrict__ ebv, const float* __restrict__ ebu,
    const float* __restrict__ ew) {
    extern __shared__ char smem[];
    const uint32_t sb = smem_to_u32(smem);
    const int tid = threadIdx.x;
    const int pair = blockIdx.z;
    const int e = g_sel_e[pair];
    const int nb = blockIdx.x, m0 = blockIdx.y * 128;

    float acc[2][8][4] = {};
    mm_core<H_, H_ / 32>(g_hhi + ((size_t)pair * N_ + m0) * H_,
                         g_hlo + ((size_t)pair * N_ + m0) * H_,
                         g_wvu_hi + ((size_t)(e * 4 + nb) * 128) * H_,
                         g_wvu_lo + ((size_t)(e * 4 + nb) * 128) * H_, sb, tid, acc);
    __syncthreads();   // pipeline buffers dead before av_s reuse

    float* av_s = (float*)smem;   // [128][65]
    const int lane = tid & 31, wid = tid >> 5;
    const int wm = wid & 3, wn = wid >> 2;
    const int l4 = lane >> 2, q2 = (lane & 3) * 2;

    if (wn == 0) {   // V half: cols 0-63 of combined tile = a-cols nb*64 + c
        #pragma unroll
        for (int mt = 0; mt < 2; mt++) {
            #pragma unroll
            for (int rh = 0; rh < 2; rh++) {
                int lrow = wm * 32 + mt * 16 + l4 + rh * 8;
                #pragma unroll
                for (int nt = 0; nt < 8; nt++) {
                    int c = nt * 8 + q2;
                    int a = nb * 64 + c;
                    av_s[lrow * 65 + c]     = tanhf(acc[mt][nt][2 * rh]     + ebv[e * A_ + a]);
                    av_s[lrow * 65 + c + 1] = tanhf(acc[mt][nt][2 * rh + 1] + ebv[e * A_ + a + 1]);
                }
            }
        }
    }
    __syncthreads();
    if (wn == 1) {   // U half: combined cols 64-127 -> a-cols nb*64 + c
        #pragma unroll
        for (int mt = 0; mt < 2; mt++) {
            #pragma unroll
            for (int rh = 0; rh < 2; rh++) {
                int lrow = wm * 32 + mt * 16 + l4 + rh * 8;
                float s = 0.f;
                #pragma unroll
                for (int nt = 0; nt < 8; nt++) {
                    int c = nt * 8 + q2;
                    int a = nb * 64 + c;
                    float u0 = 1.f / (1.f + expf(-(acc[mt][nt][2 * rh]     + ebu[e * A_ + a])));
                    float u1 = 1.f / (1.f + expf(-(acc[mt][nt][2 * rh + 1] + ebu[e * A_ + a + 1])));
                    s += av_s[lrow * 65 + c]     * u0 * ew[e * A_ + a];
                    s += av_s[lrow * 65 + c + 1] * u1 * ew[e * A_ + a + 1];
                }
                s += __shfl_xor_sync(0xffffffffu, s, 1);
                s += __shfl_xor_sync(0xffffffffu, s, 2);
                if ((lane & 3) == 0) atomicAdd(&g_scores[pair * N_ + m0 + lrow], s);
            }
        }
    }
}

// ======================= small kernels =======================
__global__ void k_zero() {
    int i = blockIdx.x * blockDim.x + threadIdx.x;
    if (i < B_ * H_) g_r[i] = 0.f;
}

__global__ void k_score_init(const float* __restrict__ ebw) {
    int i = blockIdx.x * blockDim.x + threadIdx.x;
    if (i < NPAIR * N_) g_scores[i] = ebw[g_sel_e[i / N_]];
}

__global__ void k_router_head(const float* __restrict__ fcW,
                              const float* __restrict__ fcb,
                              float* __restrict__ out) {
    __shared__ float lg[B_][E_];
    int t = threadIdx.x;
    if (t < B_ * E_) {
        int b = t / E_, e = t % E_;
        float s = fcb[e];
        for (int h = 0; h < H_; h++) s += g_r[b * H_ + h] * fcW[h * E_ + e];
        lg[b][e] = s;
    }
    __syncthreads();
    if (t < B_) {
        int b = t;
        float m = lg[b][0];
        #pragma unroll
        for (int e = 1; e < E_; e++) m = fmaxf(m, lg[b][e]);
        float p[E_]; float s = 0.f;
        #pragma unroll
        for (int e = 0; e < E_; e++) { p[e] = expf(lg[b][e] - m); s += p[e]; }
        float inv = 1.f / s;
        #pragma unroll
        for (int e = 0; e < E_; e++) {
            p[e] *= inv;
            out[B_ * L_ + B_ * C_ + b * E_ + e] = p[e];
        }
        int i0 = 0;
        #pragma unroll
        for (int e = 1; e < E_; e++) if (p[e] > p[i0]) i0 = e;
        int i1 = (i0 == 0) ? 1 : 0;
        #pragma unroll
        for (int e = 0; e < E_; e++) if (e != i1 && e != i0 && p[e] > p[i1]) i1 = e;
        float denom = p[i0] + p[i1] + 1e-8f;
        g_sel_e[2 * b + 0] = i0; g_sel_w[2 * b + 0] = p[i0] / denom;
        g_sel_e[2 * b + 1] = i1; g_sel_w[2 * b + 1] = p[i1] / denom;
    }
    for (int i = t; i < B_ * L_ + B_ * C_; i += blockDim.x) out[i] = 0.f;
}

// ---------------------------------------------------------------------------
// K5a: per (pair, 128-col block): softmax over N (recomputed) + pooled GEMV
// ---------------------------------------------------------------------------
__global__ __launch_bounds__(256) void k_pool() {
    __shared__ float attn[N_];
    __shared__ float red[256];
    __shared__ float2 red2[256];
    const int pair = blockIdx.y;
    const int col0 = blockIdx.x * 128;
    const int t = threadIdx.x;

    const float* sc = g_scores + pair * N_;
    float m = -1e30f;
    for (int i = t; i < N_; i += 256) { float v = sc[i]; attn[i] = v; m = fmaxf(m, v); }
    red[t] = m; __syncthreads();
    for (int s = 128; s > 0; s >>= 1) {
        if (t < s) red[t] = fmaxf(red[t], red[t + s]);
        __syncthreads();
    }
    m = red[0]; __syncthreads();
    float ssum = 0.f;
    for (int i = t; i < N_; i += 256) { float ev = expf(attn[i] - m); attn[i] = ev; ssum += ev; }
    red[t] = ssum; __syncthreads();
    for (int s = 128; s > 0; s >>= 1) {
        if (t < s) red[t] += red[t + s];
        __syncthreads();
    }
    const float inv = 1.f / red[0];
    __syncthreads();

    const int c2 = (t & 63) * 2, q = t >> 6;
    const __nv_bfloat162* hh = (const __nv_bfloat162*)(g_hhi + (size_t)pair * N_ * H_);
    const __nv_bfloat162* hl = (const __nv_bfloat162*)(g_hlo + (size_t)pair * N_ * H_);
    const int base = (col0 + c2) >> 1;
    float2 acc = {0.f, 0.f};
    #pragma unroll 4
    for (int n = q * 256; n < q * 256 + 256; n++) {
        float wn = attn[n];
        __nv_bfloat162 a = hh[(size_t)n * (H_ / 2) + base];
        __nv_bfloat162 b = hl[(size_t)n * (H_ / 2) + base];
        acc.x += wn * (__bfloat162float(a.x) + __bfloat162float(b.x));
        acc.y += wn * (__bfloat162float(a.y) + __bfloat162float(b.y));
    }
    red2[t] = acc;
    __syncthreads();
    if (t < 64) {
        float sx = red2[t].x + red2[t + 64].x + red2[t + 128].x + red2[t + 192].x;
        float sy = red2[t].y + red2[t + 64].y + red2[t + 128].y + red2[t + 192].y;
        g_pooled[pair * H_ + col0 + t * 2]     = sx * inv;
        g_pooled[pair * H_ + col0 + t * 2 + 1] = sy * inv;
    }
}

// ---------------------------------------------------------------------------
// K5b: per pair: latent/logit heads + weighted atomic combine into d_out
// ---------------------------------------------------------------------------
__global__ __launch_bounds__(64) void k_head(
    const float* __restrict__ eW2, const float* __restrict__ eb2,
    const float* __restrict__ eWc, const float* __restrict__ ebc,
    float* __restrict__ out) {
    __shared__ float lat[L_];
    const int pair = blockIdx.x;
    const int e = g_sel_e[pair], b = pair >> 1;
    const float w = g_sel_w[pair];
    const int t = threadIdx.x;

    const float* pl = g_pooled + pair * H_;
    float acc = eb2[e * L_ + t];
    #pragma unroll 4
    for (int h = 0; h < H_; h++) acc += pl[h] * eW2[((size_t)e * H_ + h) * L_ + t];
    float lv = fmaxf(acc, 0.f);
    lat[t] = lv;
    atomicAdd(&out[b * L_ + t], w * lv);
    __syncthreads();
    if (t < C_) {
        float a2 = ebc[e * C_ + t];
        #pragma unroll
        for (int l = 0; l < L_; l++) a2 += lat[l] * eWc[((size_t)e * L_ + l) * C_ + t];
        atomicAdd(&out[B_ * L_ + b * C_ + t], w * a2);
    }
}

// ---------------------------------------------------------------------------
extern "C" void kernel_launch(void* const* d_in, const int* in_sizes, int n_in,
                              void* d_out, int out_size) {
    const float* x        = (const float*)d_in[0];
    const float* router_W = (const float*)d_in[1];
    const float* router_b = (const float*)d_in[2];
    const float* fc_W     = (const float*)d_in[3];
    const float* fc_b     = (const float*)d_in[4];
    const float* eW1      = (const float*)d_in[5];
    const float* eb1      = (const float*)d_in[6];
    const float* eWv      = (const float*)d_in[7];
    const float* ebv      = (const float*)d_in[8];
    const float* eWu      = (const float*)d_in[9];
    const float* ebu      = (const float*)d_in[10];
    const float* ew       = (const float*)d_in[11];
    const float* ebw      = (const float*)d_in[12];
    const float* eW2      = (const float*)d_in[13];
    const float* eb2      = (const float*)d_in[14];
    const float* eWc      = (const float*)d_in[15];
    const float* ebc      = (const float*)d_in[16];
    float* out = (float*)d_out;

    static bool attr_done = false;
    if (!attr_done) {
        cudaFuncSetAttribute(k_mm_router, cudaFuncAttributeMaxDynamicSharedMemorySize,
                             MM_SMEM);
        cudaFuncSetAttribute(k_mm_expert, cudaFuncAttributeMaxDynamicSharedMemorySize,
                             MM_SMEM);
        cudaFuncSetAttribute(k_mm_score, cudaFuncAttributeMaxDynamicSharedMemorySize,
                             MM_SMEM);
        attr_done = true;
    }

    k_conv_x<<<(B_ * N_ * D_) / 1024, 256>>>(x);
    k_conv_w<<<dim3(D_ / 32, H_ / 32, E_ + 1), dim3(32, 8)>>>(router_W, eW1);
    k_conv_wsc<<<dim3(H_ / 32, A_ / 32, 2 * E_), dim3(32, 8)>>>(eWv, eWu);
    k_zero<<<(B_ * H_ + 255) / 256, 256>>>();
    k_mm_router<<<dim3(H_ / 128, (B_ * N_) / 128), 256, MM_SMEM>>>(router_b);
    k_router_head<<<1, 256>>>(fc_W, fc_b, out);
    k_score_init<<<(NPAIR * N_) / 256, 256>>>(ebw);
    k_mm_expert<<<dim3(H_ / 128, N_ / 128, NPAIR), 256, MM_SMEM>>>(eb1);
    k_mm_score<<<dim3(A_ / 64, N_ / 128, NPAIR), 256, MM_SMEM>>>(ebv, ebu, ew);
    k_pool<<<dim3(H_ / 128, NPAIR), 256>>>();
    k_head<<<NPAIR, 64>>>(eW2, eb2, eWc, ebc, out);
}

// round 16
// speedup vs baseline: 1.3680x; 1.3680x over previous
#include <cuda_runtime.h>
#include <cuda_fp16.h>
#include <math.h>
#include <stdint.h>

#define B_ 16
#define N_ 1024
#define D_ 2048
#define E_ 8
#define H_ 512
#define A_ 256
#define L_ 64
#define C_ 8
#define NPAIR 32   // B_ * TOP_K

// ---- scratch (static device globals; no allocation anywhere) ----
__device__ float g_r[B_ * H_];
__device__ float g_scores[NPAIR * N_];
__device__ float g_pooled[NPAIR * H_];
__device__ int   g_sel_e[NPAIR];
__device__ float g_sel_w[NPAIR];
__device__ __half g_xhi[(size_t)B_ * N_ * D_];   // 64 MB
__device__ __half g_xlo[(size_t)B_ * N_ * D_];   // 64 MB
__device__ __half g_hhi[(size_t)NPAIR * N_ * H_];   // 32 MB
__device__ __half g_hlo[(size_t)NPAIR * N_ * H_];   // 32 MB
__device__ __half g_w1t[(size_t)E_ * H_ * D_];   // 16 MB (K-major)
__device__ __half g_rwt[(size_t)H_ * D_];        // 2 MB  (K-major)
// combined Wv|Wu, layout [e][4 blocks][64 V-rows + 64 U-rows][H]
__device__ __half g_wvu[(size_t)E_ * 512 * H_];  // 4 MB

// ======================= base-PTX helpers =======================
__device__ __forceinline__ uint32_t smem_to_u32(const void* p) {
    uint32_t a;
    asm("{ .reg .u64 t; cvta.to.shared.u64 t, %1; cvt.u32.u64 %0, t; }"
        : "=r"(a) : "l"(p));
    return a;
}
__device__ __forceinline__ void cp_async16(uint32_t dst, const void* src) {
    asm volatile("cp.async.ca.shared.global [%0], [%1], 16;"
                 :: "r"(dst), "l"(src) : "memory");
}
#define CP_COMMIT() asm volatile("cp.async.commit_group;" ::: "memory")
#define CP_WAIT1()  asm volatile("cp.async.wait_group 1;" ::: "memory")

__device__ __forceinline__ void ldmx4(uint32_t* r, uint32_t addr) {
    asm volatile("ldmatrix.sync.aligned.m8n8.x4.shared.b16 {%0,%1,%2,%3}, [%4];"
        : "=r"(r[0]), "=r"(r[1]), "=r"(r[2]), "=r"(r[3]) : "r"(addr));
}
__device__ __forceinline__ void mma_f16(float* c, const uint32_t* a,
                                        const uint32_t* b) {
    asm volatile(
        "mma.sync.aligned.m16n8k16.row.col.f32.f16.f16.f32 "
        "{%0,%1,%2,%3}, {%4,%5,%6,%7}, {%8,%9}, {%0,%1,%2,%3};"
        : "+f"(c[0]), "+f"(c[1]), "+f"(c[2]), "+f"(c[3])
        : "r"(a[0]), "r"(a[1]), "r"(a[2]), "r"(a[3]),
          "r"(b[0]), "r"(b[1]));
}

// ======================= conversion kernels =======================
__global__ __launch_bounds__(256) void k_conv_x(const float* __restrict__ x) {
    size_t i = ((size_t)blockIdx.x * 256 + threadIdx.x) * 4;
    float4 v = *(const float4*)(x + i);
    __half h0 = __float2half_rn(v.x), h1 = __float2half_rn(v.y);
    __half h2 = __float2half_rn(v.z), h3 = __float2half_rn(v.w);
    __half l0 = __float2half_rn(v.x - __half2float(h0));
    __half l1 = __float2half_rn(v.y - __half2float(h1));
    __half l2 = __float2half_rn(v.z - __half2float(h2));
    __half l3 = __float2half_rn(v.w - __half2float(h3));
    *(__half2*)(g_xhi + i)     = __halves2half2(h0, h1);
    *(__half2*)(g_xhi + i + 2) = __halves2half2(h2, h3);
    *(__half2*)(g_xlo + i)     = __halves2half2(l0, l1);
    *(__half2*)(g_xlo + i + 2) = __halves2half2(l2, l3);
}

// transpose W1: src [D_,H_] row-major -> dst [H_,D_] (K-major), single fp16
__global__ void k_conv_w(const float* __restrict__ routerW,
                         const float* __restrict__ eW1) {
    __shared__ float t[32][33];
    const int z = blockIdx.z;
    const float* src = z ? (eW1 + (size_t)(z - 1) * D_ * H_) : routerW;
    __half* dh = z ? (g_w1t + (size_t)(z - 1) * H_ * D_) : g_rwt;
    const int k0 = blockIdx.x * 32, n0 = blockIdx.y * 32;
    #pragma unroll
    for (int i = 0; i < 4; i++) {
        int k = k0 + threadIdx.y + i * 8;
        t[threadIdx.y + i * 8][threadIdx.x] = src[(size_t)k * H_ + n0 + threadIdx.x];
    }
    __syncthreads();
    #pragma unroll
    for (int i = 0; i < 4; i++) {
        int n = n0 + threadIdx.y + i * 8;
        dh[(size_t)n * D_ + k0 + threadIdx.x] =
            __float2half_rn(t[threadIdx.x][threadIdx.y + i * 8]);
    }
}

// transpose Wv/Wu into combined layout, single fp16:
// dst row for a-col a: (a>>6)*128 + (a&63) + 64*isU  (within expert e)
__global__ void k_conv_wsc(const float* __restrict__ eWv,
                           const float* __restrict__ eWu) {
    __shared__ float t[32][33];
    const int z = blockIdx.z;
    const int e = z & 7, isU = z >> 3;
    const float* src = (isU ? eWu : eWv) + (size_t)e * H_ * A_;
    const int h0 = blockIdx.x * 32, a0 = blockIdx.y * 32;
    #pragma unroll
    for (int i = 0; i < 4; i++) {
        int h = h0 + threadIdx.y + i * 8;
        t[threadIdx.y + i * 8][threadIdx.x] = src[(size_t)h * A_ + a0 + threadIdx.x];
    }
    __syncthreads();
    #pragma unroll
    for (int i = 0; i < 4; i++) {
        int a = a0 + threadIdx.y + i * 8;
        size_t row = (size_t)e * 512 + (a >> 6) * 128 + (a & 63) + 64 * isU;
        g_wvu[row * H_ + h0 + threadIdx.x] =
            __float2half_rn(t[threadIdx.x][threadIdx.y + i * 8]);
    }
}

// ======================= mma.sync GEMM core (fp16, 2-term, 3-stage) ========
// Block tile 128x128, K-chunks of 32 fp16 (64 B/row). 8 warps, warp tile 32x64.
// 3 arrays per stage: Ah, Al, B. smem row = 64 B,
// chunk swizzle: c ^= (row>>1)&3  -> conflict-free ldmatrix.
#define ARRB   (128 * 64)       // 8192
#define STAGEB (3 * ARRB)       // 24576
#define NSTG   3
#define MM_SMEM (NSTG * STAGEB) // 73728 -> 2 CTAs/SM

__device__ __forceinline__ uint32_t swz(int row, int chunk) {
    return (uint32_t)(row * 64 + ((chunk ^ ((row >> 1) & 3)) << 4));
}

template<int LDK>
__device__ __forceinline__ void mm_load_stage(
    uint32_t sb, int stg, int k0, int tid,
    const __half* Ah, const __half* Al, const __half* Bw) {
    const __half* ps[3] = {Ah, Al, Bw};
    uint32_t base = sb + stg * STAGEB;
    int row0 = tid >> 2, c = tid & 3;
    #pragma unroll
    for (int arr = 0; arr < 3; arr++) {
        #pragma unroll
        for (int half = 0; half < 2; half++) {
            int row = row0 + half * 64;
            cp_async16(base + arr * ARRB + swz(row, c),
                       ps[arr] + (size_t)row * LDK + k0 + c * 8);
        }
    }
}

template<int LDK, int NCHUNK>
__device__ __forceinline__ void mm_core(
    const __half* __restrict__ Ah, const __half* __restrict__ Al,
    const __half* __restrict__ Bw,
    uint32_t sb, int tid, float acc[2][8][4]) {
    const int lane = tid & 31, wid = tid >> 5;
    const int wm = wid & 3, wn = wid >> 2;

    mm_load_stage<LDK>(sb, 0, 0, tid, Ah, Al, Bw);  CP_COMMIT();
    mm_load_stage<LDK>(sb, 1, 32, tid, Ah, Al, Bw); CP_COMMIT();

    const int a_row = lane & 15, a_ch = lane >> 4;       // chunk bit
    const int b_row = ((lane >> 4) & 1) * 8 + (lane & 7);
    const int b_ch = (lane >> 3) & 1;

    for (int s = 0; s < NCHUNK; s++) {
        CP_WAIT1();
        __syncthreads();
        if (s + 2 < NCHUNK)
            mm_load_stage<LDK>(sb, (s + 2) % NSTG, (s + 2) * 32, tid, Ah, Al, Bw);
        CP_COMMIT();

        const uint32_t b0 = sb + (s % NSTG) * STAGEB;
        #pragma unroll
        for (int ks = 0; ks < 2; ks++) {       // two k16 slices
            uint32_t ah[2][4], al[2][4], bw[8][2];
            uint32_t ra[2];
            #pragma unroll
            for (int mt = 0; mt < 2; mt++) {
                ra[mt] = b0 + swz(wm * 32 + mt * 16 + a_row, ks * 2 + a_ch);
                ldmx4(ah[mt], ra[mt]);
            }
            #pragma unroll
            for (int np = 0; np < 4; np++) {
                uint32_t rb = b0 + 2 * ARRB + swz(wn * 64 + np * 16 + b_row, ks * 2 + b_ch);
                ldmx4(&bw[2 * np][0], rb);
            }
            #pragma unroll
            for (int mt = 0; mt < 2; mt++)
                #pragma unroll
                for (int nt = 0; nt < 8; nt++)
                    mma_f16(acc[mt][nt], ah[mt], bw[nt]);
            #pragma unroll
            for (int mt = 0; mt < 2; mt++)
                ldmx4(al[mt], ra[mt] + ARRB);
            #pragma unroll
            for (int mt = 0; mt < 2; mt++)
                #pragma unroll
                for (int nt = 0; nt < 8; nt++)
                    mma_f16(acc[mt][nt], al[mt], bw[nt]);
        }
    }
}

// ---------------------------------------------------------------------------
// K1: router GEMM: relu(x@W + b), mean over N -> atomic into g_r
// ---------------------------------------------------------------------------
__global__ __launch_bounds__(256, 2) void k_mm_router(const float* __restrict__ rb) {
    extern __shared__ char smem[];
    const uint32_t sb = smem_to_u32(smem);
    const int tid = threadIdx.x;
    const int n0 = blockIdx.x * 128, m0 = blockIdx.y * 128;

    float acc[2][8][4] = {};
    mm_core<D_, D_ / 32>(g_xhi + (size_t)m0 * D_, g_xlo + (size_t)m0 * D_,
                         g_rwt + (size_t)n0 * D_, sb, tid, acc);

    const int lane = tid & 31, wid = tid >> 5;
    const int wn = wid >> 2;
    const int l4 = lane >> 2, q2 = (lane & 3) * 2;
    const int b = m0 / N_;
    #pragma unroll
    for (int nt = 0; nt < 8; nt++) {
        int col = n0 + wn * 64 + nt * 8 + q2;
        float bx = rb[col], by = rb[col + 1];
        float s0 = 0.f, s1 = 0.f;
        #pragma unroll
        for (int mt = 0; mt < 2; mt++) {
            s0 += fmaxf(acc[mt][nt][0] + bx, 0.f) + fmaxf(acc[mt][nt][2] + bx, 0.f);
            s1 += fmaxf(acc[mt][nt][1] + by, 0.f) + fmaxf(acc[mt][nt][3] + by, 0.f);
        }
        s0 += __shfl_xor_sync(0xffffffffu, s0, 4);
        s0 += __shfl_xor_sync(0xffffffffu, s0, 8);
        s0 += __shfl_xor_sync(0xffffffffu, s0, 16);
        s1 += __shfl_xor_sync(0xffffffffu, s1, 4);
        s1 += __shfl_xor_sync(0xffffffffu, s1, 8);
        s1 += __shfl_xor_sync(0xffffffffu, s1, 16);
        if (l4 == 0) {
            atomicAdd(&g_r[b * H_ + col],     s0 * (1.f / N_));
            atomicAdd(&g_r[b * H_ + col + 1], s1 * (1.f / N_));
        }
    }
}

// ---------------------------------------------------------------------------
// K3: expert GEMM: h = relu(x_b @ eW1[e] + eb1[e]) -> split-fp16 g_hhi/g_hlo
// ---------------------------------------------------------------------------
__global__ __launch_bounds__(256, 2) void k_mm_expert(const float* __restrict__ eb1) {
    extern __shared__ char smem[];
    const uint32_t sb = smem_to_u32(smem);
    const int tid = threadIdx.x;
    const int pair = blockIdx.z;
    const int e = g_sel_e[pair], b = pair >> 1;
    const int n0 = blockIdx.x * 128, m0 = blockIdx.y * 128;

    float acc[2][8][4] = {};
    mm_core<D_, D_ / 32>(g_xhi + ((size_t)b * N_ + m0) * D_,
                         g_xlo + ((size_t)b * N_ + m0) * D_,
                         g_w1t + ((size_t)e * H_ + n0) * D_, sb, tid, acc);

    const int lane = tid & 31, wid = tid >> 5;
    const int wm = wid & 3, wn = wid >> 2;
    const int l4 = lane >> 2, q2 = (lane & 3) * 2;
    __half* hh = g_hhi + (size_t)pair * N_ * H_;
    __half* hl = g_hlo + (size_t)pair * N_ * H_;
    #pragma unroll
    for (int mt = 0; mt < 2; mt++) {
        #pragma unroll
        for (int rh = 0; rh < 2; rh++) {
            int row = m0 + wm * 32 + mt * 16 + l4 + rh * 8;
            #pragma unroll
            for (int nt = 0; nt < 8; nt++) {
                int col = n0 + wn * 64 + nt * 8 + q2;
                float v0 = fmaxf(acc[mt][nt][2 * rh] + eb1[e * H_ + col], 0.f);
                float v1 = fmaxf(acc[mt][nt][2 * rh + 1] + eb1[e * H_ + col + 1], 0.f);
                __half h0 = __float2half_rn(v0);
                __half h1 = __float2half_rn(v1);
                __half l0 = __float2half_rn(v0 - __half2float(h0));
                __half l1 = __float2half_rn(v1 - __half2float(h1));
                *(__half2*)&hh[(size_t)row * H_ + col] = __halves2half2(h0, h1);
                *(__half2*)&hl[(size_t)row * H_ + col] = __halves2half2(l0, l1);
            }
        }
    }
}

// ---------------------------------------------------------------------------
// K4: merged score GEMM: one pass computes V (cols 0-63) and U (cols 64-127)
// of a 64-a-col block. V warps stash tanh in smem; U warps combine + reduce.
// grid (A_/64=4, N_/128=8, NPAIR)
// ---------------------------------------------------------------------------
__global__ __launch_bounds__(256, 2) void k_mm_score(
    const float* __restrict__ ebv, const float* __restrict__ ebu,
    const float* __restrict__ ew) {
    extern __shared__ char smem[];
    const uint32_t sb = smem_to_u32(smem);
    const int tid = threadIdx.x;
    const int pair = blockIdx.z;
    const int e = g_sel_e[pair];
    const int nb = blockIdx.x, m0 = blockIdx.y * 128;

    float acc[2][8][4] = {};
    mm_core<H_, H_ / 32>(g_hhi + ((size_t)pair * N_ + m0) * H_,
                         g_hlo + ((size_t)pair * N_ + m0) * H_,
                         g_wvu + ((size_t)(e * 4 + nb) * 128) * H_, sb, tid, acc);
    __syncthreads();   // pipeline buffers dead before av_s reuse

    float* av_s = (float*)smem;   // [128][65]
    const int lane = tid & 31, wid = tid >> 5;
    const int wm = wid & 3, wn = wid >> 2;
    const int l4 = lane >> 2, q2 = (lane & 3) * 2;

    if (wn == 0) {   // V half: cols 0-63 of combined tile = a-cols nb*64 + c
        #pragma unroll
        for (int mt = 0; mt < 2; mt++) {
            #pragma unroll
            for (int rh = 0; rh < 2; rh++) {
                int lrow = wm * 32 + mt * 16 + l4 + rh * 8;
                #pragma unroll
                for (int nt = 0; nt < 8; nt++) {
                    int c = nt * 8 + q2;
                    int a = nb * 64 + c;
                    av_s[lrow * 65 + c]     = tanhf(acc[mt][nt][2 * rh]     + ebv[e * A_ + a]);
                    av_s[lrow * 65 + c + 1] = tanhf(acc[mt][nt][2 * rh + 1] + ebv[e * A_ + a + 1]);
                }
            }
        }
    }
    __syncthreads();
    if (wn == 1) {   // U half: combined cols 64-127 -> a-cols nb*64 + c
        #pragma unroll
        for (int mt = 0; mt < 2; mt++) {
            #pragma unroll
            for (int rh = 0; rh < 2; rh++) {
                int lrow = wm * 32 + mt * 16 + l4 + rh * 8;
                float s = 0.f;
                #pragma unroll
                for (int nt = 0; nt < 8; nt++) {
                    int c = nt * 8 + q2;
                    int a = nb * 64 + c;
                    float u0 = 1.f / (1.f + expf(-(acc[mt][nt][2 * rh]     + ebu[e * A_ + a])));
                    float u1 = 1.f / (1.f + expf(-(acc[mt][nt][2 * rh + 1] + ebu[e * A_ + a + 1])));
                    s += av_s[lrow * 65 + c]     * u0 * ew[e * A_ + a];
                    s += av_s[lrow * 65 + c + 1] * u1 * ew[e * A_ + a + 1];
                }
                s += __shfl_xor_sync(0xffffffffu, s, 1);
                s += __shfl_xor_sync(0xffffffffu, s, 2);
                if ((lane & 3) == 0) atomicAdd(&g_scores[pair * N_ + m0 + lrow], s);
            }
        }
    }
}

// ======================= small kernels =======================
__global__ void k_zero() {
    int i = blockIdx.x * blockDim.x + threadIdx.x;
    if (i < B_ * H_) g_r[i] = 0.f;
}

__global__ void k_score_init(const float* __restrict__ ebw) {
    int i = blockIdx.x * blockDim.x + threadIdx.x;
    if (i < NPAIR * N_) g_scores[i] = ebw[g_sel_e[i / N_]];
}

__global__ void k_router_head(const float* __restrict__ fcW,
                              const float* __restrict__ fcb,
                              float* __restrict__ out) {
    __shared__ float lg[B_][E_];
    int t = threadIdx.x;
    if (t < B_ * E_) {
        int b = t / E_, e = t % E_;
        float s = fcb[e];
        for (int h = 0; h < H_; h++) s += g_r[b * H_ + h] * fcW[h * E_ + e];
        lg[b][e] = s;
    }
    __syncthreads();
    if (t < B_) {
        int b = t;
        float m = lg[b][0];
        #pragma unroll
        for (int e = 1; e < E_; e++) m = fmaxf(m, lg[b][e]);
        float p[E_]; float s = 0.f;
        #pragma unroll
        for (int e = 0; e < E_; e++) { p[e] = expf(lg[b][e] - m); s += p[e]; }
        float inv = 1.f / s;
        #pragma unroll
        for (int e = 0; e < E_; e++) {
            p[e] *= inv;
            out[B_ * L_ + B_ * C_ + b * E_ + e] = p[e];
        }
        int i0 = 0;
        #pragma unroll
        for (int e = 1; e < E_; e++) if (p[e] > p[i0]) i0 = e;
        int i1 = (i0 == 0) ? 1 : 0;
        #pragma unroll
        for (int e = 0; e < E_; e++) if (e != i1 && e != i0 && p[e] > p[i1]) i1 = e;
        float denom = p[i0] + p[i1] + 1e-8f;
        g_sel_e[2 * b + 0] = i0; g_sel_w[2 * b + 0] = p[i0] / denom;
        g_sel_e[2 * b + 1] = i1; g_sel_w[2 * b + 1] = p[i1] / denom;
    }
    for (int i = t; i < B_ * L_ + B_ * C_; i += blockDim.x) out[i] = 0.f;
}

// ---------------------------------------------------------------------------
// K5a: per (pair, 128-col block): softmax over N (recomputed) + pooled GEMV
// ---------------------------------------------------------------------------
__global__ __launch_bounds__(256) void k_pool() {
    __shared__ float attn[N_];
    __shared__ float red[256];
    __shared__ float2 red2[256];
    const int pair = blockIdx.y;
    const int col0 = blockIdx.x * 128;
    const int t = threadIdx.x;

    const float* sc = g_scores + pair * N_;
    float m = -1e30f;
    for (int i = t; i < N_; i += 256) { float v = sc[i]; attn[i] = v; m = fmaxf(m, v); }
    red[t] = m; __syncthreads();
    for (int s = 128; s > 0; s >>= 1) {
        if (t < s) red[t] = fmaxf(red[t], red[t + s]);
        __syncthreads();
    }
    m = red[0]; __syncthreads();
    float ssum = 0.f;
    for (int i = t; i < N_; i += 256) { float ev = expf(attn[i] - m); attn[i] = ev; ssum += ev; }
    red[t] = ssum; __syncthreads();
    for (int s = 128; s > 0; s >>= 1) {
        if (t < s) red[t] += red[t + s];
        __syncthreads();
    }
    const float inv = 1.f / red[0];
    __syncthreads();

    const int c2 = (t & 63) * 2, q = t >> 6;
    const __half2* hh = (const __half2*)(g_hhi + (size_t)pair * N_ * H_);
    const __half2* hl = (const __half2*)(g_hlo + (size_t)pair * N_ * H_);
    const int base = (col0 + c2) >> 1;
    float2 acc = {0.f, 0.f};
    #pragma unroll 4
    for (int n = q * 256; n < q * 256 + 256; n++) {
        float wn = attn[n];
        float2 a = __half22float2(hh[(size_t)n * (H_ / 2) + base]);
        float2 b = __half22float2(hl[(size_t)n * (H_ / 2) + base]);
        acc.x += wn * (a.x + b.x);
        acc.y += wn * (a.y + b.y);
    }
    red2[t] = acc;
    __syncthreads();
    if (t < 64) {
        float sx = red2[t].x + red2[t + 64].x + red2[t + 128].x + red2[t + 192].x;
        float sy = red2[t].y + red2[t + 64].y + red2[t + 128].y + red2[t + 192].y;
        g_pooled[pair * H_ + col0 + t * 2]     = sx * inv;
        g_pooled[pair * H_ + col0 + t * 2 + 1] = sy * inv;
    }
}

// ---------------------------------------------------------------------------
// K5b: per pair: latent/logit heads + weighted atomic combine into d_out
// ---------------------------------------------------------------------------
__global__ __launch_bounds__(64) void k_head(
    const float* __restrict__ eW2, const float* __restrict__ eb2,
    const float* __restrict__ eWc, const float* __restrict__ ebc,
    float* __restrict__ out) {
    __shared__ float lat[L_];
    const int pair = blockIdx.x;
    const int e = g_sel_e[pair], b = pair >> 1;
    const float w = g_sel_w[pair];
    const int t = threadIdx.x;

    const float* pl = g_pooled + pair * H_;
    float acc = eb2[e * L_ + t];
    #pragma unroll 4
    for (int h = 0; h < H_; h++) acc += pl[h] * eW2[((size_t)e * H_ + h) * L_ + t];
    float lv = fmaxf(acc, 0.f);
    lat[t] = lv;
    atomicAdd(&out[b * L_ + t], w * lv);
    __syncthreads();
    if (t < C_) {
        float a2 = ebc[e * C_ + t];
        #pragma unroll
        for (int l = 0; l < L_; l++) a2 += lat[l] * eWc[((size_t)e * L_ + l) * C_ + t];
        atomicAdd(&out[B_ * L_ + b * C_ + t], w * a2);
    }
}

// ---------------------------------------------------------------------------
extern "C" void kernel_launch(void* const* d_in, const int* in_sizes, int n_in,
                              void* d_out, int out_size) {
    const float* x        = (const float*)d_in[0];
    const float* router_W = (const float*)d_in[1];
    const float* router_b = (const float*)d_in[2];
    const float* fc_W     = (const float*)d_in[3];
    const float* fc_b     = (const float*)d_in[4];
    const float* eW1      = (const float*)d_in[5];
    const float* eb1      = (const float*)d_in[6];
    const float* eWv      = (const float*)d_in[7];
    const float* ebv      = (const float*)d_in[8];
    const float* eWu      = (const float*)d_in[9];
    const float* ebu      = (const float*)d_in[10];
    const float* ew       = (const float*)d_in[11];
    const float* ebw      = (const float*)d_in[12];
    const float* eW2      = (const float*)d_in[13];
    const float* eb2      = (const float*)d_in[14];
    const float* eWc      = (const float*)d_in[15];
    const float* ebc      = (const float*)d_in[16];
    float* out = (float*)d_out;

    static bool attr_done = false;
    if (!attr_done) {
        cudaFuncSetAttribute(k_mm_router, cudaFuncAttributeMaxDynamicSharedMemorySize,
                             MM_SMEM);
        cudaFuncSetAttribute(k_mm_expert, cudaFuncAttributeMaxDynamicSharedMemorySize,
                             MM_SMEM);
        cudaFuncSetAttribute(k_mm_score, cudaFuncAttributeMaxDynamicSharedMemorySize,
                             MM_SMEM);
        attr_done = true;
    }

    k_conv_x<<<(B_ * N_ * D_) / 1024, 256>>>(x);
    k_conv_w<<<dim3(D_ / 32, H_ / 32, E_ + 1), dim3(32, 8)>>>(router_W, eW1);
    k_conv_wsc<<<dim3(H_ / 32, A_ / 32, 2 * E_), dim3(32, 8)>>>(eWv, eWu);
    k_zero<<<(B_ * H_ + 255) / 256, 256>>>();
    k_mm_router<<<dim3(H_ / 128, (B_ * N_) / 128), 256, MM_SMEM>>>(router_b);
    k_router_head<<<1, 256>>>(fc_W, fc_b, out);
    k_score_init<<<(NPAIR * N_) / 256, 256>>>(ebw);
    k_mm_expert<<<dim3(H_ / 128, N_ / 128, NPAIR), 256, MM_SMEM>>>(eb1);
    k_mm_score<<<dim3(A_ / 64, N_ / 128, NPAIR), 256, MM_SMEM>>>(ebv, ebu, ew);
    k_pool<<<dim3(H_ / 128, NPAIR), 256>>>();
    k_head<<<NPAIR, 64>>>(eW2, eb2, eWc, ebc, out);
}

// round 17
// speedup vs baseline: 1.4285x; 1.0442x over previous
#include <cuda_runtime.h>
#include <cuda_fp16.h>
#include <math.h>
#include <stdint.h>

#define B_ 16
#define N_ 1024
#define D_ 2048
#define E_ 8
#define H_ 512
#define A_ 256
#define L_ 64
#define C_ 8
#define NPAIR 32   // B_ * TOP_K

// ---- scratch (static device globals; no allocation anywhere) ----
__device__ float g_r[B_ * H_];
__device__ float g_scores[NPAIR * N_];
__device__ float g_pooled[NPAIR * H_];
__device__ int   g_sel_e[NPAIR];
__device__ float g_sel_w[NPAIR];
__device__ __half g_x16[(size_t)B_ * N_ * D_];   // 64 MB
__device__ __half g_h16[(size_t)NPAIR * N_ * H_];   // 32 MB
__device__ __half g_w1t[(size_t)E_ * H_ * D_];   // 16 MB (K-major)
__device__ __half g_rwt[(size_t)H_ * D_];        // 2 MB  (K-major)
// combined Wv|Wu, layout [e][4 blocks][64 V-rows + 64 U-rows][H]
__device__ __half g_wvu[(size_t)E_ * 512 * H_];  // 4 MB

// ======================= base-PTX helpers =======================
__device__ __forceinline__ uint32_t smem_to_u32(const void* p) {
    uint32_t a;
    asm("{ .reg .u64 t; cvta.to.shared.u64 t, %1; cvt.u32.u64 %0, t; }"
        : "=r"(a) : "l"(p));
    return a;
}
__device__ __forceinline__ void cp_async16(uint32_t dst, const void* src) {
    asm volatile("cp.async.ca.shared.global [%0], [%1], 16;"
                 :: "r"(dst), "l"(src) : "memory");
}
#define CP_COMMIT() asm volatile("cp.async.commit_group;" ::: "memory")
#define CP_WAIT2()  asm volatile("cp.async.wait_group 2;" ::: "memory")

__device__ __forceinline__ void ldmx4(uint32_t* r, uint32_t addr) {
    asm volatile("ldmatrix.sync.aligned.m8n8.x4.shared.b16 {%0,%1,%2,%3}, [%4];"
        : "=r"(r[0]), "=r"(r[1]), "=r"(r[2]), "=r"(r[3]) : "r"(addr));
}
__device__ __forceinline__ void mma_f16(float* c, const uint32_t* a,
                                        const uint32_t* b) {
    asm volatile(
        "mma.sync.aligned.m16n8k16.row.col.f32.f16.f16.f32 "
        "{%0,%1,%2,%3}, {%4,%5,%6,%7}, {%8,%9}, {%0,%1,%2,%3};"
        : "+f"(c[0]), "+f"(c[1]), "+f"(c[2]), "+f"(c[3])
        : "r"(a[0]), "r"(a[1]), "r"(a[2]), "r"(a[3]),
          "r"(b[0]), "r"(b[1]));
}

// ======================= conversion kernels =======================
__global__ __launch_bounds__(256) void k_conv_x(const float* __restrict__ x) {
    size_t i = ((size_t)blockIdx.x * 256 + threadIdx.x) * 4;
    float4 v = *(const float4*)(x + i);
    *(__half2*)(g_x16 + i)     = __halves2half2(__float2half_rn(v.x), __float2half_rn(v.y));
    *(__half2*)(g_x16 + i + 2) = __halves2half2(__float2half_rn(v.z), __float2half_rn(v.w));
}

// transpose W1: src [D_,H_] row-major -> dst [H_,D_] (K-major), single fp16
__global__ void k_conv_w(const float* __restrict__ routerW,
                         const float* __restrict__ eW1) {
    __shared__ float t[32][33];
    const int z = blockIdx.z;
    const float* src = z ? (eW1 + (size_t)(z - 1) * D_ * H_) : routerW;
    __half* dh = z ? (g_w1t + (size_t)(z - 1) * H_ * D_) : g_rwt;
    const int k0 = blockIdx.x * 32, n0 = blockIdx.y * 32;
    #pragma unroll
    for (int i = 0; i < 4; i++) {
        int k = k0 + threadIdx.y + i * 8;
        t[threadIdx.y + i * 8][threadIdx.x] = src[(size_t)k * H_ + n0 + threadIdx.x];
    }
    __syncthreads();
    #pragma unroll
    for (int i = 0; i < 4; i++) {
        int n = n0 + threadIdx.y + i * 8;
        dh[(size_t)n * D_ + k0 + threadIdx.x] =
            __float2half_rn(t[threadIdx.x][threadIdx.y + i * 8]);
    }
}

// transpose Wv/Wu into combined layout, single fp16:
// dst row for a-col a: (a>>6)*128 + (a&63) + 64*isU  (within expert e)
__global__ void k_conv_wsc(const float* __restrict__ eWv,
                           const float* __restrict__ eWu) {
    __shared__ float t[32][33];
    const int z = blockIdx.z;
    const int e = z & 7, isU = z >> 3;
    const float* src = (isU ? eWu : eWv) + (size_t)e * H_ * A_;
    const int h0 = blockIdx.x * 32, a0 = blockIdx.y * 32;
    #pragma unroll
    for (int i = 0; i < 4; i++) {
        int h = h0 + threadIdx.y + i * 8;
        t[threadIdx.y + i * 8][threadIdx.x] = src[(size_t)h * A_ + a0 + threadIdx.x];
    }
    __syncthreads();
    #pragma unroll
    for (int i = 0; i < 4; i++) {
        int a = a0 + threadIdx.y + i * 8;
        size_t row = (size_t)e * 512 + (a >> 6) * 128 + (a & 63) + 64 * isU;
        g_wvu[row * H_ + h0 + threadIdx.x] =
            __float2half_rn(t[threadIdx.x][threadIdx.y + i * 8]);
    }
}

// ======================= mma.sync GEMM core (fp16 single, 4-stage) =========
// Block tile 128x128, K-chunks of 32 fp16 (64 B/row). 8 warps, warp tile 32x64.
// 2 arrays per stage: A, B. smem row = 64 B,
// chunk swizzle: c ^= (row>>1)&3  -> conflict-free ldmatrix.
#define ARRB   (128 * 64)       // 8192
#define STAGEB (2 * ARRB)       // 16384
#define NSTG   4
#define MM_SMEM (NSTG * STAGEB) // 65536 -> 2 CTAs/SM

__device__ __forceinline__ uint32_t swz(int row, int chunk) {
    return (uint32_t)(row * 64 + ((chunk ^ ((row >> 1) & 3)) << 4));
}

template<int LDK>
__device__ __forceinline__ void mm_load_stage(
    uint32_t sb, int stg, int k0, int tid,
    const __half* A, const __half* Bw) {
    const __half* ps[2] = {A, Bw};
    uint32_t base = sb + stg * STAGEB;
    int row0 = tid >> 2, c = tid & 3;
    #pragma unroll
    for (int arr = 0; arr < 2; arr++) {
        #pragma unroll
        for (int half = 0; half < 2; half++) {
            int row = row0 + half * 64;
            cp_async16(base + arr * ARRB + swz(row, c),
                       ps[arr] + (size_t)row * LDK + k0 + c * 8);
        }
    }
}

template<int LDK, int NCHUNK>
__device__ __forceinline__ void mm_core(
    const __half* __restrict__ A, const __half* __restrict__ Bw,
    uint32_t sb, int tid, float acc[2][8][4]) {
    const int lane = tid & 31, wid = tid >> 5;
    const int wm = wid & 3, wn = wid >> 2;

    mm_load_stage<LDK>(sb, 0, 0, tid, A, Bw);  CP_COMMIT();
    mm_load_stage<LDK>(sb, 1, 32, tid, A, Bw); CP_COMMIT();
    mm_load_stage<LDK>(sb, 2, 64, tid, A, Bw); CP_COMMIT();

    const int a_row = lane & 15, a_ch = lane >> 4;       // chunk bit
    const int b_row = ((lane >> 4) & 1) * 8 + (lane & 7);
    const int b_ch = (lane >> 3) & 1;

    for (int s = 0; s < NCHUNK; s++) {
        CP_WAIT2();
        __syncthreads();
        if (s + 3 < NCHUNK)
            mm_load_stage<LDK>(sb, (s + 3) % NSTG, (s + 3) * 32, tid, A, Bw);
        CP_COMMIT();

        const uint32_t b0 = sb + (s % NSTG) * STAGEB;
        #pragma unroll
        for (int ks = 0; ks < 2; ks++) {       // two k16 slices
            uint32_t ah[2][4], bw[8][2];
            #pragma unroll
            for (int mt = 0; mt < 2; mt++)
                ldmx4(ah[mt], b0 + swz(wm * 32 + mt * 16 + a_row, ks * 2 + a_ch));
            #pragma unroll
            for (int np = 0; np < 4; np++)
                ldmx4(&bw[2 * np][0],
                      b0 + ARRB + swz(wn * 64 + np * 16 + b_row, ks * 2 + b_ch));
            #pragma unroll
            for (int mt = 0; mt < 2; mt++)
                #pragma unroll
                for (int nt = 0; nt < 8; nt++)
                    mma_f16(acc[mt][nt], ah[mt], bw[nt]);
        }
    }
}

// ---------------------------------------------------------------------------
// K1: router GEMM: relu(x@W + b), mean over N -> atomic into g_r
// ---------------------------------------------------------------------------
__global__ __launch_bounds__(256, 2) void k_mm_router(const float* __restrict__ rb) {
    extern __shared__ char smem[];
    const uint32_t sb = smem_to_u32(smem);
    const int tid = threadIdx.x;
    const int n0 = blockIdx.x * 128, m0 = blockIdx.y * 128;

    float acc[2][8][4] = {};
    mm_core<D_, D_ / 32>(g_x16 + (size_t)m0 * D_,
                         g_rwt + (size_t)n0 * D_, sb, tid, acc);

    const int lane = tid & 31, wid = tid >> 5;
    const int wn = wid >> 2;
    const int l4 = lane >> 2, q2 = (lane & 3) * 2;
    const int b = m0 / N_;
    #pragma unroll
    for (int nt = 0; nt < 8; nt++) {
        int col = n0 + wn * 64 + nt * 8 + q2;
        float bx = rb[col], by = rb[col + 1];
        float s0 = 0.f, s1 = 0.f;
        #pragma unroll
        for (int mt = 0; mt < 2; mt++) {
            s0 += fmaxf(acc[mt][nt][0] + bx, 0.f) + fmaxf(acc[mt][nt][2] + bx, 0.f);
            s1 += fmaxf(acc[mt][nt][1] + by, 0.f) + fmaxf(acc[mt][nt][3] + by, 0.f);
        }
        s0 += __shfl_xor_sync(0xffffffffu, s0, 4);
        s0 += __shfl_xor_sync(0xffffffffu, s0, 8);
        s0 += __shfl_xor_sync(0xffffffffu, s0, 16);
        s1 += __shfl_xor_sync(0xffffffffu, s1, 4);
        s1 += __shfl_xor_sync(0xffffffffu, s1, 8);
        s1 += __shfl_xor_sync(0xffffffffu, s1, 16);
        if (l4 == 0) {
            atomicAdd(&g_r[b * H_ + col],     s0 * (1.f / N_));
            atomicAdd(&g_r[b * H_ + col + 1], s1 * (1.f / N_));
        }
    }
}

// ---------------------------------------------------------------------------
// K3: expert GEMM: h = relu(x_b @ eW1[e] + eb1[e]) -> single fp16 g_h16
// ---------------------------------------------------------------------------
__global__ __launch_bounds__(256, 2) void k_mm_expert(const float* __restrict__ eb1) {
    extern __shared__ char smem[];
    const uint32_t sb = smem_to_u32(smem);
    const int tid = threadIdx.x;
    const int pair = blockIdx.z;
    const int e = g_sel_e[pair], b = pair >> 1;
    const int n0 = blockIdx.x * 128, m0 = blockIdx.y * 128;

    float acc[2][8][4] = {};
    mm_core<D_, D_ / 32>(g_x16 + ((size_t)b * N_ + m0) * D_,
                         g_w1t + ((size_t)e * H_ + n0) * D_, sb, tid, acc);

    const int lane = tid & 31, wid = tid >> 5;
    const int wm = wid & 3, wn = wid >> 2;
    const int l4 = lane >> 2, q2 = (lane & 3) * 2;
    __half* hh = g_h16 + (size_t)pair * N_ * H_;
    #pragma unroll
    for (int mt = 0; mt < 2; mt++) {
        #pragma unroll
        for (int rh = 0; rh < 2; rh++) {
            int row = m0 + wm * 32 + mt * 16 + l4 + rh * 8;
            #pragma unroll
            for (int nt = 0; nt < 8; nt++) {
                int col = n0 + wn * 64 + nt * 8 + q2;
                float v0 = fmaxf(acc[mt][nt][2 * rh] + eb1[e * H_ + col], 0.f);
                float v1 = fmaxf(acc[mt][nt][2 * rh + 1] + eb1[e * H_ + col + 1], 0.f);
                *(__half2*)&hh[(size_t)row * H_ + col] =
                    __halves2half2(__float2half_rn(v0), __float2half_rn(v1));
            }
        }
    }
}

// ---------------------------------------------------------------------------
// K4: merged score GEMM: one pass computes V (cols 0-63) and U (cols 64-127)
// of a 64-a-col block. V warps stash tanh in smem; U warps combine + reduce.
// grid (A_/64=4, N_/128=8, NPAIR)
// ---------------------------------------------------------------------------
__global__ __launch_bounds__(256, 2) void k_mm_score(
    const float* __restrict__ ebv, const float* __restrict__ ebu,
    const float* __restrict__ ew) {
    extern __shared__ char smem[];
    const uint32_t sb = smem_to_u32(smem);
    const int tid = threadIdx.x;
    const int pair = blockIdx.z;
    const int e = g_sel_e[pair];
    const int nb = blockIdx.x, m0 = blockIdx.y * 128;

    float acc[2][8][4] = {};
    mm_core<H_, H_ / 32>(g_h16 + ((size_t)pair * N_ + m0) * H_,
                         g_wvu + ((size_t)(e * 4 + nb) * 128) * H_, sb, tid, acc);
    __syncthreads();   // pipeline buffers dead before av_s reuse

    float* av_s = (float*)smem;   // [128][65]
    const int lane = tid & 31, wid = tid >> 5;
    const int wm = wid & 3, wn = wid >> 2;
    const int l4 = lane >> 2, q2 = (lane & 3) * 2;

    if (wn == 0) {   // V half: cols 0-63 of combined tile = a-cols nb*64 + c
        #pragma unroll
        for (int mt = 0; mt < 2; mt++) {
            #pragma unroll
            for (int rh = 0; rh < 2; rh++) {
                int lrow = wm * 32 + mt * 16 + l4 + rh * 8;
                #pragma unroll
                for (int nt = 0; nt < 8; nt++) {
                    int c = nt * 8 + q2;
                    int a = nb * 64 + c;
                    av_s[lrow * 65 + c]     = tanhf(acc[mt][nt][2 * rh]     + ebv[e * A_ + a]);
                    av_s[lrow * 65 + c + 1] = tanhf(acc[mt][nt][2 * rh + 1] + ebv[e * A_ + a + 1]);
                }
            }
        }
    }
    __syncthreads();
    if (wn == 1) {   // U half: combined cols 64-127 -> a-cols nb*64 + c
        #pragma unroll
        for (int mt = 0; mt < 2; mt++) {
            #pragma unroll
            for (int rh = 0; rh < 2; rh++) {
                int lrow = wm * 32 + mt * 16 + l4 + rh * 8;
                float s = 0.f;
                #pragma unroll
                for (int nt = 0; nt < 8; nt++) {
                    int c = nt * 8 + q2;
                    int a = nb * 64 + c;
                    float u0 = 1.f / (1.f + expf(-(acc[mt][nt][2 * rh]     + ebu[e * A_ + a])));
                    float u1 = 1.f / (1.f + expf(-(acc[mt][nt][2 * rh + 1] + ebu[e * A_ + a + 1])));
                    s += av_s[lrow * 65 + c]     * u0 * ew[e * A_ + a];
                    s += av_s[lrow * 65 + c + 1] * u1 * ew[e * A_ + a + 1];
                }
                s += __shfl_xor_sync(0xffffffffu, s, 1);
                s += __shfl_xor_sync(0xffffffffu, s, 2);
                if ((lane & 3) == 0) atomicAdd(&g_scores[pair * N_ + m0 + lrow], s);
            }
        }
    }
}

// ======================= small kernels =======================
__global__ void k_zero() {
    int i = blockIdx.x * blockDim.x + threadIdx.x;
    if (i < B_ * H_) g_r[i] = 0.f;
}

__global__ void k_score_init(const float* __restrict__ ebw) {
    int i = blockIdx.x * blockDim.x + threadIdx.x;
    if (i < NPAIR * N_) g_scores[i] = ebw[g_sel_e[i / N_]];
}

__global__ void k_router_head(const float* __restrict__ fcW,
                              const float* __restrict__ fcb,
                              float* __restrict__ out) {
    __shared__ float lg[B_][E_];
    int t = threadIdx.x;
    if (t < B_ * E_) {
        int b = t / E_, e = t % E_;
        float s = fcb[e];
        for (int h = 0; h < H_; h++) s += g_r[b * H_ + h] * fcW[h * E_ + e];
        lg[b][e] = s;
    }
    __syncthreads();
    if (t < B_) {
        int b = t;
        float m = lg[b][0];
        #pragma unroll
        for (int e = 1; e < E_; e++) m = fmaxf(m, lg[b][e]);
        float p[E_]; float s = 0.f;
        #pragma unroll
        for (int e = 0; e < E_; e++) { p[e] = expf(lg[b][e] - m); s += p[e]; }
        float inv = 1.f / s;
        #pragma unroll
        for (int e = 0; e < E_; e++) {
            p[e] *= inv;
            out[B_ * L_ + B_ * C_ + b * E_ + e] = p[e];
        }
        int i0 = 0;
        #pragma unroll
        for (int e = 1; e < E_; e++) if (p[e] > p[i0]) i0 = e;
        int i1 = (i0 == 0) ? 1 : 0;
        #pragma unroll
        for (int e = 0; e < E_; e++) if (e != i1 && e != i0 && p[e] > p[i1]) i1 = e;
        float denom = p[i0] + p[i1] + 1e-8f;
        g_sel_e[2 * b + 0] = i0; g_sel_w[2 * b + 0] = p[i0] / denom;
        g_sel_e[2 * b + 1] = i1; g_sel_w[2 * b + 1] = p[i1] / denom;
    }
    for (int i = t; i < B_ * L_ + B_ * C_; i += blockDim.x) out[i] = 0.f;
}

// ---------------------------------------------------------------------------
// K5a: per (pair, 128-col block): softmax over N (recomputed) + pooled GEMV
// ---------------------------------------------------------------------------
__global__ __launch_bounds__(256) void k_pool() {
    __shared__ float attn[N_];
    __shared__ float red[256];
    __shared__ float2 red2[256];
    const int pair = blockIdx.y;
    const int col0 = blockIdx.x * 128;
    const int t = threadIdx.x;

    const float* sc = g_scores + pair * N_;
    float m = -1e30f;
    for (int i = t; i < N_; i += 256) { float v = sc[i]; attn[i] = v; m = fmaxf(m, v); }
    red[t] = m; __syncthreads();
    for (int s = 128; s > 0; s >>= 1) {
        if (t < s) red[t] = fmaxf(red[t], red[t + s]);
        __syncthreads();
    }
    m = red[0]; __syncthreads();
    float ssum = 0.f;
    for (int i = t; i < N_; i += 256) { float ev = expf(attn[i] - m); attn[i] = ev; ssum += ev; }
    red[t] = ssum; __syncthreads();
    for (int s = 128; s > 0; s >>= 1) {
        if (t < s) red[t] += red[t + s];
        __syncthreads();
    }
    const float inv = 1.f / red[0];
    __syncthreads();

    const int c2 = (t & 63) * 2, q = t >> 6;
    const __half2* hh = (const __half2*)(g_h16 + (size_t)pair * N_ * H_);
    const int base = (col0 + c2) >> 1;
    float2 acc = {0.f, 0.f};
    #pragma unroll 4
    for (int n = q * 256; n < q * 256 + 256; n++) {
        float wn = attn[n];
        float2 a = __half22float2(hh[(size_t)n * (H_ / 2) + base]);
        acc.x += wn * a.x;
        acc.y += wn * a.y;
    }
    red2[t] = acc;
    __syncthreads();
    if (t < 64) {
        float sx = red2[t].x + red2[t + 64].x + red2[t + 128].x + red2[t + 192].x;
        float sy = red2[t].y + red2[t + 64].y + red2[t + 128].y + red2[t + 192].y;
        g_pooled[pair * H_ + col0 + t * 2]     = sx * inv;
        g_pooled[pair * H_ + col0 + t * 2 + 1] = sy * inv;
    }
}

// ---------------------------------------------------------------------------
// K5b: per pair: latent/logit heads + weighted atomic combine into d_out
// ---------------------------------------------------------------------------
__global__ __launch_bounds__(64) void k_head(
    const float* __restrict__ eW2, const float* __restrict__ eb2,
    const float* __restrict__ eWc, const float* __restrict__ ebc,
    float* __restrict__ out) {
    __shared__ float lat[L_];
    const int pair = blockIdx.x;
    const int e = g_sel_e[pair], b = pair >> 1;
    const float w = g_sel_w[pair];
    const int t = threadIdx.x;

    const float* pl = g_pooled + pair * H_;
    float acc = eb2[e * L_ + t];
    #pragma unroll 4
    for (int h = 0; h < H_; h++) acc += pl[h] * eW2[((size_t)e * H_ + h) * L_ + t];
    float lv = fmaxf(acc, 0.f);
    lat[t] = lv;
    atomicAdd(&out[b * L_ + t], w * lv);
    __syncthreads();
    if (t < C_) {
        float a2 = ebc[e * C_ + t];
        #pragma unroll
        for (int l = 0; l < L_; l++) a2 += lat[l] * eWc[((size_t)e * L_ + l) * C_ + t];
        atomicAdd(&out[B_ * L_ + b * C_ + t], w * a2);
    }
}

// ---------------------------------------------------------------------------
extern "C" void kernel_launch(void* const* d_in, const int* in_sizes, int n_in,
                              void* d_out, int out_size) {
    const float* x        = (const float*)d_in[0];
    const float* router_W = (const float*)d_in[1];
    const float* router_b = (const float*)d_in[2];
    const float* fc_W     = (const float*)d_in[3];
    const float* fc_b     = (const float*)d_in[4];
    const float* eW1      = (const float*)d_in[5];
    const float* eb1      = (const float*)d_in[6];
    const float* eWv      = (const float*)d_in[7];
    const float* ebv      = (const float*)d_in[8];
    const float* eWu      = (const float*)d_in[9];
    const float* ebu      = (const float*)d_in[10];
    const float* ew       = (const float*)d_in[11];
    const float* ebw      = (const float*)d_in[12];
    const float* eW2      = (const float*)d_in[13];
    const float* eb2      = (const float*)d_in[14];
    const float* eWc      = (const float*)d_in[15];
    const float* ebc      = (const float*)d_in[16];
    float* out = (float*)d_out;

    static bool attr_done = false;
    if (!attr_done) {
        cudaFuncSetAttribute(k_mm_router, cudaFuncAttributeMaxDynamicSharedMemorySize,
                             MM_SMEM);
        cudaFuncSetAttribute(k_mm_expert, cudaFuncAttributeMaxDynamicSharedMemorySize,
                             MM_SMEM);
        cudaFuncSetAttribute(k_mm_score, cudaFuncAttributeMaxDynamicSharedMemorySize,
                             MM_SMEM);
        attr_done = true;
    }

    k_conv_x<<<(B_ * N_ * D_) / 1024, 256>>>(x);
    k_conv_w<<<dim3(D_ / 32, H_ / 32, E_ + 1), dim3(32, 8)>>>(router_W, eW1);
    k_conv_wsc<<<dim3(H_ / 32, A_ / 32, 2 * E_), dim3(32, 8)>>>(eWv, eWu);
    k_zero<<<(B_ * H_ + 255) / 256, 256>>>();
    k_mm_router<<<dim3(H_ / 128, (B_ * N_) / 128), 256, MM_SMEM>>>(router_b);
    k_router_head<<<1, 256>>>(fc_W, fc_b, out);
    k_score_init<<<(NPAIR * N_) / 256, 256>>>(ebw);
    k_mm_expert<<<dim3(H_ / 128, N_ / 128, NPAIR), 256, MM_SMEM>>>(eb1);
    k_mm_score<<<dim3(A_ / 64, N_ / 128, NPAIR), 256, MM_SMEM>>>(ebv, ebu, ew);
    k_pool<<<dim3(H_ / 128, NPAIR), 256>>>();
    k_head<<<NPAIR, 64>>>(eW2, eb2, eWc, ebc, out);
}